// round 7
// baseline (speedup 1.0000x reference)
#include <cuda_runtime.h>
#include <cstdint>
#include <cstddef>

// Problem constants
constexpr int SEQ   = 1024;
constexpr int HIDC  = 1024;
constexpr int NHC   = 32;
constexpr int HDC   = 32;
constexpr int BATCH = 4;
constexpr int MR    = BATCH * SEQ;   // 4096 rows

// Scratch
__device__ float g_q[(size_t)MR * HIDC];
__device__ float g_k[(size_t)MR * HIDC];
__device__ float g_v[(size_t)MR * HIDC];
__device__ float g_ctx[(size_t)MR * HIDC];
__device__ float g_x[(size_t)MR * HIDC];

__device__ __forceinline__ uint32_t f2tf32(float x) {
    uint32_t r;
    asm("cvt.rna.tf32.f32 %0, %1;" : "=r"(r) : "f"(x));
    return r;
}

__device__ __forceinline__ void mma_tf32(float* c, const uint32_t* a, const uint32_t* b) {
    asm volatile(
        "mma.sync.aligned.m16n8k8.row.col.f32.tf32.tf32.f32 "
        "{%0,%1,%2,%3}, {%4,%5,%6,%7}, {%8,%9}, {%0,%1,%2,%3};\n"
        : "+f"(c[0]), "+f"(c[1]), "+f"(c[2]), "+f"(c[3])
        : "r"(a[0]), "r"(a[1]), "r"(a[2]), "r"(a[3]), "r"(b[0]), "r"(b[1]));
}

// ---------------------------------------------------------------------------
// 3xTF32 tensor-core GEMM (unchanged from R5): C = A @ B^T + bias (+resid)
// ---------------------------------------------------------------------------
constexpr int LDT = 20;

__device__ __forceinline__ void gemm_tc_body(const float* __restrict__ A,
                                             const float* __restrict__ B,
                                             const float* __restrict__ bias,
                                             const float* __restrict__ resid,
                                             float* __restrict__ C)
{
    __shared__ uint32_t sAh[128 * LDT], sAl[128 * LDT];
    __shared__ uint32_t sBh[128 * LDT], sBl[128 * LDT];

    const int t    = threadIdx.x;
    const int m0   = blockIdx.y * 128;
    const int n0   = blockIdx.x * 128;
    const int wid  = t >> 5, lane = t & 31;
    const int wm   = wid & 1, wn = wid >> 1;
    const int g    = lane >> 2, t4 = lane & 3;

    const int lr = t >> 2;
    const int lq = (t & 3) * 4;
    const float* Ap = A + (size_t)(m0 + lr) * HIDC + lq;
    const float* Bp = B + (size_t)(n0 + lr) * HIDC + lq;

    float acc[4][4][4];
#pragma unroll
    for (int i = 0; i < 4; i++)
#pragma unroll
        for (int j = 0; j < 4; j++)
#pragma unroll
            for (int r = 0; r < 4; r++) acc[i][j][r] = 0.f;

    float4 ra0 = *(const float4*)(Ap);
    float4 ra1 = *(const float4*)(Ap + (size_t)64 * HIDC);
    float4 rb0 = *(const float4*)(Bp);
    float4 rb1 = *(const float4*)(Bp + (size_t)64 * HIDC);

    for (int kt = 0; kt < HIDC / 16; kt++) {
        __syncthreads();
        {
            uint32_t h[4], l[4];
            h[0] = f2tf32(ra0.x); l[0] = f2tf32(ra0.x - __uint_as_float(h[0]));
            h[1] = f2tf32(ra0.y); l[1] = f2tf32(ra0.y - __uint_as_float(h[1]));
            h[2] = f2tf32(ra0.z); l[2] = f2tf32(ra0.z - __uint_as_float(h[2]));
            h[3] = f2tf32(ra0.w); l[3] = f2tf32(ra0.w - __uint_as_float(h[3]));
            *(uint4*)&sAh[lr * LDT + lq] = *(uint4*)h;
            *(uint4*)&sAl[lr * LDT + lq] = *(uint4*)l;
            h[0] = f2tf32(ra1.x); l[0] = f2tf32(ra1.x - __uint_as_float(h[0]));
            h[1] = f2tf32(ra1.y); l[1] = f2tf32(ra1.y - __uint_as_float(h[1]));
            h[2] = f2tf32(ra1.z); l[2] = f2tf32(ra1.z - __uint_as_float(h[2]));
            h[3] = f2tf32(ra1.w); l[3] = f2tf32(ra1.w - __uint_as_float(h[3]));
            *(uint4*)&sAh[(lr + 64) * LDT + lq] = *(uint4*)h;
            *(uint4*)&sAl[(lr + 64) * LDT + lq] = *(uint4*)l;
            h[0] = f2tf32(rb0.x); l[0] = f2tf32(rb0.x - __uint_as_float(h[0]));
            h[1] = f2tf32(rb0.y); l[1] = f2tf32(rb0.y - __uint_as_float(h[1]));
            h[2] = f2tf32(rb0.z); l[2] = f2tf32(rb0.z - __uint_as_float(h[2]));
            h[3] = f2tf32(rb0.w); l[3] = f2tf32(rb0.w - __uint_as_float(h[3]));
            *(uint4*)&sBh[lr * LDT + lq] = *(uint4*)h;
            *(uint4*)&sBl[lr * LDT + lq] = *(uint4*)l;
            h[0] = f2tf32(rb1.x); l[0] = f2tf32(rb1.x - __uint_as_float(h[0]));
            h[1] = f2tf32(rb1.y); l[1] = f2tf32(rb1.y - __uint_as_float(h[1]));
            h[2] = f2tf32(rb1.z); l[2] = f2tf32(rb1.z - __uint_as_float(h[2]));
            h[3] = f2tf32(rb1.w); l[3] = f2tf32(rb1.w - __uint_as_float(h[3]));
            *(uint4*)&sBh[(lr + 64) * LDT + lq] = *(uint4*)h;
            *(uint4*)&sBl[(lr + 64) * LDT + lq] = *(uint4*)l;
        }
        __syncthreads();

        if (kt + 1 < HIDC / 16) {
            const float* Ap2 = Ap + (kt + 1) * 16;
            const float* Bp2 = Bp + (kt + 1) * 16;
            ra0 = *(const float4*)(Ap2);
            ra1 = *(const float4*)(Ap2 + (size_t)64 * HIDC);
            rb0 = *(const float4*)(Bp2);
            rb1 = *(const float4*)(Bp2 + (size_t)64 * HIDC);
        }

#pragma unroll
        for (int ks = 0; ks < 2; ks++) {
            const int kb = ks * 8 + t4;
            uint32_t bh[4][2], bl[4][2];
#pragma unroll
            for (int nf = 0; nf < 4; nf++) {
                const int n = (wn * 32 + nf * 8 + g) * LDT;
                bh[nf][0] = sBh[n + kb];
                bh[nf][1] = sBh[n + kb + 4];
                bl[nf][0] = sBl[n + kb];
                bl[nf][1] = sBl[n + kb + 4];
            }
#pragma unroll
            for (int mf = 0; mf < 4; mf++) {
                const int m = (wm * 64 + mf * 16 + g) * LDT;
                uint32_t ah[4], al[4];
                ah[0] = sAh[m + kb];
                ah[1] = sAh[m + 8 * LDT + kb];
                ah[2] = sAh[m + kb + 4];
                ah[3] = sAh[m + 8 * LDT + kb + 4];
                al[0] = sAl[m + kb];
                al[1] = sAl[m + 8 * LDT + kb];
                al[2] = sAl[m + kb + 4];
                al[3] = sAl[m + 8 * LDT + kb + 4];
#pragma unroll
                for (int nf = 0; nf < 4; nf++) {
                    mma_tf32(acc[mf][nf], ah, bh[nf]);
                    mma_tf32(acc[mf][nf], ah, bl[nf]);
                    mma_tf32(acc[mf][nf], al, bh[nf]);
                }
            }
        }
    }

#pragma unroll
    for (int mf = 0; mf < 4; mf++) {
#pragma unroll
        for (int nf = 0; nf < 4; nf++) {
            const int row = m0 + wm * 64 + mf * 16 + g;
            const int col = n0 + wn * 32 + nf * 8 + t4 * 2;
            float2 bb = *(const float2*)(bias + col);
            float2 o0, o1;
            o0.x = acc[mf][nf][0] + bb.x;
            o0.y = acc[mf][nf][1] + bb.y;
            o1.x = acc[mf][nf][2] + bb.x;
            o1.y = acc[mf][nf][3] + bb.y;
            if (resid != nullptr) {
                float2 r0 = *(const float2*)(resid + (size_t)row * HIDC + col);
                float2 r1 = *(const float2*)(resid + (size_t)(row + 8) * HIDC + col);
                o0.x += r0.x; o0.y += r0.y;
                o1.x += r1.x; o1.y += r1.y;
            }
            *(float2*)(C + (size_t)row * HIDC + col)       = o0;
            *(float2*)(C + (size_t)(row + 8) * HIDC + col) = o1;
        }
    }
}

__global__ __launch_bounds__(256, 2) void qkv_gemm(const float* __restrict__ H,
    const float* __restrict__ Wq, const float* __restrict__ bq,
    const float* __restrict__ Wk, const float* __restrict__ bk,
    const float* __restrict__ Wv, const float* __restrict__ bv)
{
    const float* W;
    const float* bias;
    float* out;
    if (blockIdx.z == 0)      { W = Wq; bias = bq; out = g_q; }
    else if (blockIdx.z == 1) { W = Wk; bias = bk; out = g_k; }
    else                      { W = Wv; bias = bv; out = g_v; }
    gemm_tc_body(H, W, bias, nullptr, out);
}

__global__ __launch_bounds__(256, 2) void o_gemm(const float* __restrict__ Wo,
    const float* __restrict__ bo, const float* __restrict__ H)
{
    gemm_tc_body(g_ctx, Wo, bo, H, g_x);
}

// ---------------------------------------------------------------------------
// Tensor-core fused attention. Per block: (b, h, 32 q-rows).
//  Phase 1: S = (Q K^T + bias)/sqrt(32) via 3xTF32 mma, S in smem (32x1024)
//  Phase 2: exact softmax; write probs to gmem; normalized P back to S
//  Phase 3: ctx^T = V^T P^T via 3xTF32 mma (roles swapped so V stages like K)
// ---------------------------------------------------------------------------
constexpr int SST = 1032;   // S smem row stride
constexpr int KST = 33;     // K/V/Q smem row stride (tf32 words)

constexpr int OFF_S  = 0;                 // 32*1032 = 33024 floats
constexpr int OFF_KH = 33024;             // 256*33  = 8448
constexpr int OFF_KL = OFF_KH + 8448;     // 8448
constexpr int OFF_QH = OFF_KL + 8448;     // 32*33 = 1056
constexpr int OFF_QL = OFF_QH + 1056;     // 1056
constexpr int OFF_BS = OFF_QL + 1056;     // 1056
constexpr int ATTN_FLOATS = OFF_BS + 1056;  // 53088
constexpr size_t ATTN_SMEM_BYTES = (size_t)ATTN_FLOATS * sizeof(float);

__global__ __launch_bounds__(256, 1) void attn_kernel(const float* __restrict__ dist_emb,
                                                      float* __restrict__ probs_out)
{
    extern __shared__ float sm[];
    float*    S  = sm + OFF_S;
    uint32_t* kh = (uint32_t*)(sm + OFF_KH);
    uint32_t* kl = (uint32_t*)(sm + OFF_KL);
    uint32_t* qh = (uint32_t*)(sm + OFF_QH);
    uint32_t* ql = (uint32_t*)(sm + OFF_QL);
    float*    bs = sm + OFF_BS;

    const int t   = threadIdx.x;
    const int q0  = blockIdx.x * 32;
    const int h   = blockIdx.y;
    const int b   = blockIdx.z;
    const int wid = t >> 5, lane = t & 31;
    const int g   = lane >> 2, t4 = lane & 3;

    const size_t bh_off = (size_t)b * SEQ * HIDC + (size_t)h * HDC;
    const float* Qb = g_q + bh_off;
    const float* Kb = g_k + bh_off;
    const float* Vb = g_v + bh_off;

    // bias strip: bs[r] = dist_emb[(q0 + r)*HD + h], r in [0,1054]
    for (int r = t; r < 1055; r += 256)
        bs[r] = dist_emb[(size_t)(q0 + r) * HDC + h];

    // stage Q tile (32x32) as tf32 hi/lo
    {
        const int row = t >> 3, c4 = (t & 7) * 4;
        float4 v = *(const float4*)(Qb + (size_t)(q0 + row) * HIDC + c4);
        float vv[4] = {v.x, v.y, v.z, v.w};
#pragma unroll
        for (int j = 0; j < 4; j++) {
            uint32_t hi = f2tf32(vv[j]);
            qh[row * KST + c4 + j] = hi;
            ql[row * KST + c4 + j] = f2tf32(vv[j] - __uint_as_float(hi));
        }
    }
    __syncthreads();

    // preload Q A-fragments (reused for every key chunk)
    uint32_t qfh[2][4][4], qfl[2][4][4];
#pragma unroll
    for (int mf = 0; mf < 2; mf++)
#pragma unroll
        for (int ks = 0; ks < 4; ks++) {
            const int r0 = (mf * 16 + g) * KST;
            const int r1 = r0 + 8 * KST;
            const int k0 = ks * 8 + t4;
            qfh[mf][ks][0] = qh[r0 + k0];
            qfh[mf][ks][1] = qh[r1 + k0];
            qfh[mf][ks][2] = qh[r0 + k0 + 4];
            qfh[mf][ks][3] = qh[r1 + k0 + 4];
            qfl[mf][ks][0] = ql[r0 + k0];
            qfl[mf][ks][1] = ql[r1 + k0];
            qfl[mf][ks][2] = ql[r0 + k0 + 4];
            qfl[mf][ks][3] = ql[r1 + k0 + 4];
        }

    const float scale = 0.17677669529663688f;  // 1/sqrt(32)

    // ---- Phase 1: S = (Q K^T + bias) * scale ----
    for (int c = 0; c < 4; c++) {
        __syncthreads();
        // stage K chunk (256x32) as tf32 hi/lo
#pragma unroll
        for (int p = 0; p < 8; p++) {
            const int row = p * 32 + (t >> 3), c4 = (t & 7) * 4;
            float4 v = *(const float4*)(Kb + (size_t)(c * 256 + row) * HIDC + c4);
            float vv[4] = {v.x, v.y, v.z, v.w};
#pragma unroll
            for (int j = 0; j < 4; j++) {
                uint32_t hi = f2tf32(vv[j]);
                kh[row * KST + c4 + j] = hi;
                kl[row * KST + c4 + j] = f2tf32(vv[j] - __uint_as_float(hi));
            }
        }
        __syncthreads();

        const int kw = wid * 32;   // this warp's 32 keys within chunk
#pragma unroll
        for (int nf = 0; nf < 4; nf++) {
            uint32_t bhh[4][2], bll[4][2];
#pragma unroll
            for (int ks = 0; ks < 4; ks++) {
                const int n = (kw + nf * 8 + g) * KST + ks * 8 + t4;
                bhh[ks][0] = kh[n]; bhh[ks][1] = kh[n + 4];
                bll[ks][0] = kl[n]; bll[ks][1] = kl[n + 4];
            }
#pragma unroll
            for (int mf = 0; mf < 2; mf++) {
                float acc[4] = {0.f, 0.f, 0.f, 0.f};
#pragma unroll
                for (int ks = 0; ks < 4; ks++) {
                    mma_tf32(acc, qfh[mf][ks], bhh[ks]);
                    mma_tf32(acc, qfh[mf][ks], bll[ks]);
                    mma_tf32(acc, qfl[mf][ks], bhh[ks]);
                }
                const int row0 = mf * 16 + g;
                const int row1 = row0 + 8;
                const int col  = c * 256 + kw + nf * 8 + 2 * t4;
                float2 s0, s1;
                s0.x = (acc[0] + bs[row0 - col + 1023]) * scale;
                s0.y = (acc[1] + bs[row0 - col + 1022]) * scale;
                s1.x = (acc[2] + bs[row1 - col + 1023]) * scale;
                s1.y = (acc[3] + bs[row1 - col + 1022]) * scale;
                *(float2*)&S[row0 * SST + col] = s0;
                *(float2*)&S[row1 * SST + col] = s1;
            }
        }
    }
    __syncthreads();

    // ---- Phase 2: softmax; write probs to gmem; normalized P back to S ----
    {
        float* pb = probs_out + ((size_t)(b * NHC + h) * SEQ + q0) * SEQ;
        for (int rr = 0; rr < 4; rr++) {
            const int r = wid + 8 * rr;
            float* row = S + r * SST;
            float mx = -1e30f;
            for (int i = lane; i < 1024; i += 32) mx = fmaxf(mx, row[i]);
#pragma unroll
            for (int o = 16; o > 0; o >>= 1)
                mx = fmaxf(mx, __shfl_xor_sync(0xffffffffu, mx, o));
            float sum = 0.f;
            for (int i = lane; i < 1024; i += 32) {
                float e = __expf(row[i] - mx);
                row[i] = e;
                sum += e;
            }
#pragma unroll
            for (int o = 16; o > 0; o >>= 1)
                sum += __shfl_xor_sync(0xffffffffu, sum, o);
            const float inv = 1.f / sum;
            float* pr = pb + (size_t)r * SEQ;
            for (int i = lane; i < 1024; i += 32) {
                float p = row[i] * inv;
                row[i] = p;
                pr[i]  = p;
            }
        }
    }

    // ---- Phase 3: ctx^T = V^T @ P^T (m=dim, n=q-row, k=key) ----
    float acc[2][4][4];
#pragma unroll
    for (int mf = 0; mf < 2; mf++)
#pragma unroll
        for (int nf = 0; nf < 4; nf++)
#pragma unroll
            for (int r = 0; r < 4; r++) acc[mf][nf][r] = 0.f;

    for (int c = 0; c < 4; c++) {
        __syncthreads();
        // stage V chunk (256x32) as tf32 hi/lo (same layout as K)
#pragma unroll
        for (int p = 0; p < 8; p++) {
            const int row = p * 32 + (t >> 3), c4 = (t & 7) * 4;
            float4 v = *(const float4*)(Vb + (size_t)(c * 256 + row) * HIDC + c4);
            float vv[4] = {v.x, v.y, v.z, v.w};
#pragma unroll
            for (int j = 0; j < 4; j++) {
                uint32_t hi = f2tf32(vv[j]);
                kh[row * KST + c4 + j] = hi;
                kl[row * KST + c4 + j] = f2tf32(vv[j] - __uint_as_float(hi));
            }
        }
        __syncthreads();

        const int kw = wid * 32;
#pragma unroll
        for (int ks = 0; ks < 4; ks++) {
            const int kLoc  = kw + ks * 8 + t4;      // key within chunk
            const int kGlob = c * 256 + kLoc;        // key within sequence
            // A fragments: A[m=d][k=key] = V[key][d]
            uint32_t ah[2][4], al[2][4];
#pragma unroll
            for (int mf = 0; mf < 2; mf++) {
                const int d0 = mf * 16 + g;
                const int a0 = kLoc * KST + d0;
                const int a4 = (kLoc + 4) * KST + d0;
                ah[mf][0] = kh[a0];
                ah[mf][1] = kh[a0 + 8];
                ah[mf][2] = kh[a4];
                ah[mf][3] = kh[a4 + 8];
                al[mf][0] = kl[a0];
                al[mf][1] = kl[a0 + 8];
                al[mf][2] = kl[a4];
                al[mf][3] = kl[a4 + 8];
            }
            // B fragments: B[n=q][k=key] = P[q][key], fp32 -> tf32 hi/lo
#pragma unroll
            for (int nf = 0; nf < 4; nf++) {
                const int q = nf * 8 + g;
                const float p0 = S[q * SST + kGlob];
                const float p1 = S[q * SST + kGlob + 4];
                uint32_t bh2[2], bl2[2];
                bh2[0] = f2tf32(p0); bl2[0] = f2tf32(p0 - __uint_as_float(bh2[0]));
                bh2[1] = f2tf32(p1); bl2[1] = f2tf32(p1 - __uint_as_float(bh2[1]));
#pragma unroll
                for (int mf = 0; mf < 2; mf++) {
                    mma_tf32(acc[mf][nf], ah[mf], bh2);
                    mma_tf32(acc[mf][nf], ah[mf], bl2);
                    mma_tf32(acc[mf][nf], al[mf], bh2);
                }
            }
        }
    }
    __syncthreads();

    // cross-warp reduction of partial ctx (red reuses the K hi region: 8448 fl)
    float* red = sm + OFF_KH;
#pragma unroll
    for (int mf = 0; mf < 2; mf++)
#pragma unroll
        for (int nf = 0; nf < 4; nf++) {
            const int d = mf * 16 + g;
            const int q = nf * 8 + 2 * t4;
            float* rw = red + wid * 1056;
            rw[q * 33 + d]           = acc[mf][nf][0];
            rw[(q + 1) * 33 + d]     = acc[mf][nf][1];
            rw[q * 33 + d + 8]       = acc[mf][nf][2];
            rw[(q + 1) * 33 + d + 8] = acc[mf][nf][3];
        }
    __syncthreads();

#pragma unroll
    for (int i = 0; i < 4; i++) {
        const int idx = t + i * 256;        // 0..1023
        const int q = idx >> 5, d = idx & 31;
        float s = 0.f;
#pragma unroll
        for (int w = 0; w < 8; w++) s += red[w * 1056 + q * 33 + d];
        g_ctx[(size_t)(b * SEQ + q0 + q) * HIDC + h * HDC + d] = s;
    }
}

// ---------------------------------------------------------------------------
// LayerNorm (unchanged)
// ---------------------------------------------------------------------------
__global__ void ln_kernel(const float* __restrict__ gamma,
                          const float* __restrict__ beta,
                          float* __restrict__ out)
{
    __shared__ float red[8];
    const int row = blockIdx.x, t = threadIdx.x;
    const int w = t >> 5, lane = t & 31;

    float4 v = *((const float4*)(g_x + (size_t)row * HIDC) + t);
    float s = v.x + v.y + v.z + v.w;
#pragma unroll
    for (int o = 16; o > 0; o >>= 1) s += __shfl_xor_sync(0xffffffffu, s, o);
    if (lane == 0) red[w] = s;
    __syncthreads();
    if (t == 0) {
        float tt = 0.f;
#pragma unroll
        for (int i = 0; i < 8; i++) tt += red[i];
        red[0] = tt;
    }
    __syncthreads();
    const float mu = red[0] * (1.f / 1024.f);
    __syncthreads();

    float dx = v.x - mu, dy = v.y - mu, dz = v.z - mu, dw = v.w - mu;
    float sq = dx * dx + dy * dy + dz * dz + dw * dw;
#pragma unroll
    for (int o = 16; o > 0; o >>= 1) sq += __shfl_xor_sync(0xffffffffu, sq, o);
    if (lane == 0) red[w] = sq;
    __syncthreads();
    if (t == 0) {
        float tt = 0.f;
#pragma unroll
        for (int i = 0; i < 8; i++) tt += red[i];
        red[0] = tt;
    }
    __syncthreads();
    const float inv = rsqrtf(red[0] * (1.f / 1024.f) + 1e-12f);

    float4 g  = *((const float4*)gamma + t);
    float4 bt = *((const float4*)beta + t);
    float4 o4;
    o4.x = dx * inv * g.x + bt.x;
    o4.y = dy * inv * g.y + bt.y;
    o4.z = dz * inv * g.z + bt.z;
    o4.w = dw * inv * g.w + bt.w;
    *((float4*)(out + (size_t)row * HIDC) + t) = o4;
}

// ---------------------------------------------------------------------------
// Launch
// ---------------------------------------------------------------------------
extern "C" void kernel_launch(void* const* d_in, const int* in_sizes, int n_in,
                              void* d_out, int out_size)
{
    (void)in_sizes; (void)n_in; (void)out_size;
    const float* hidden = (const float*)d_in[0];
    const float* Wq = (const float*)d_in[1];
    const float* bq = (const float*)d_in[2];
    const float* Wk = (const float*)d_in[3];
    const float* bk = (const float*)d_in[4];
    const float* Wv = (const float*)d_in[5];
    const float* bv = (const float*)d_in[6];
    const float* Wo = (const float*)d_in[7];
    const float* bo = (const float*)d_in[8];
    const float* gamma = (const float*)d_in[9];
    const float* beta  = (const float*)d_in[10];
    const float* dist  = (const float*)d_in[11];

    float* out   = (float*)d_out;
    float* probs = out + (size_t)BATCH * SEQ * HIDC;

    cudaFuncSetAttribute(attn_kernel, cudaFuncAttributeMaxDynamicSharedMemorySize,
                         (int)ATTN_SMEM_BYTES);

    qkv_gemm<<<dim3(8, 32, 3), 256>>>(hidden, Wq, bq, Wk, bk, Wv, bv);
    attn_kernel<<<dim3(32, 32, 4), 256, ATTN_SMEM_BYTES>>>(dist, probs);
    o_gemm<<<dim3(8, 32, 1), 256>>>(Wo, bo, hidden);
    ln_kernel<<<MR, 256>>>(gamma, beta, out);
}

// round 8
// speedup vs baseline: 1.3994x; 1.3994x over previous
#include <cuda_runtime.h>
#include <cuda_bf16.h>
#include <cstdint>
#include <cstddef>

// Problem constants
constexpr int SEQ   = 1024;
constexpr int HIDC  = 1024;
constexpr int NHC   = 32;
constexpr int HDC   = 32;
constexpr int BATCH = 4;
constexpr int MR    = BATCH * SEQ;   // 4096 rows

// Scratch
__device__ float g_q[(size_t)MR * HIDC];
__device__ float g_k[(size_t)MR * HIDC];
__device__ float g_v[(size_t)MR * HIDC];
__device__ float g_ctx[(size_t)MR * HIDC];
__device__ float g_x[(size_t)MR * HIDC];

__device__ __forceinline__ uint32_t f2tf32(float x) {
    uint32_t r;
    asm("cvt.rna.tf32.f32 %0, %1;" : "=r"(r) : "f"(x));
    return r;
}

__device__ __forceinline__ void mma_tf32(float* c, const uint32_t* a, const uint32_t* b) {
    asm volatile(
        "mma.sync.aligned.m16n8k8.row.col.f32.tf32.tf32.f32 "
        "{%0,%1,%2,%3}, {%4,%5,%6,%7}, {%8,%9}, {%0,%1,%2,%3};\n"
        : "+f"(c[0]), "+f"(c[1]), "+f"(c[2]), "+f"(c[3])
        : "r"(a[0]), "r"(a[1]), "r"(a[2]), "r"(a[3]), "r"(b[0]), "r"(b[1]));
}

__device__ __forceinline__ void mma_bf16(float* c, const uint32_t* a, const uint32_t* b) {
    asm volatile(
        "mma.sync.aligned.m16n8k16.row.col.f32.bf16.bf16.f32 "
        "{%0,%1,%2,%3}, {%4,%5,%6,%7}, {%8,%9}, {%0,%1,%2,%3};\n"
        : "+f"(c[0]), "+f"(c[1]), "+f"(c[2]), "+f"(c[3])
        : "r"(a[0]), "r"(a[1]), "r"(a[2]), "r"(a[3]), "r"(b[0]), "r"(b[1]));
}

// Split f32 pair -> bf16x2 hi word + bf16x2 lo (residual) word. low half = x.
__device__ __forceinline__ void cvt_pair(float x, float y, uint32_t& hi, uint32_t& lo) {
    __nv_bfloat162 h = __float22bfloat162_rn(make_float2(x, y));
    float2 hf = __bfloat1622float2(h);
    __nv_bfloat162 l = __float22bfloat162_rn(make_float2(x - hf.x, y - hf.y));
    hi = *reinterpret_cast<uint32_t*>(&h);
    lo = *reinterpret_cast<uint32_t*>(&l);
}

// ---------------------------------------------------------------------------
// 3xBF16 tensor-core GEMM: C = A @ B^T + bias (+resid)
// CTA tile 128x128x16, 8 warps (2 M x 4 N), 2-stage smem ping-pong.
// smem rows hold 16 bf16 = 8 words; stride 12 words (conflict-free frags).
// ---------------------------------------------------------------------------
constexpr int LDB = 12;

__device__ __forceinline__ void gemm_tc_body(const float* __restrict__ A,
                                             const float* __restrict__ B,
                                             const float* __restrict__ bias,
                                             const float* __restrict__ resid,
                                             float* __restrict__ C)
{
    __shared__ uint32_t sAh[2][128 * LDB], sAl[2][128 * LDB];
    __shared__ uint32_t sBh[2][128 * LDB], sBl[2][128 * LDB];

    const int t    = threadIdx.x;
    const int m0   = blockIdx.y * 128;
    const int n0   = blockIdx.x * 128;
    const int wid  = t >> 5, lane = t & 31;
    const int wm   = wid & 1, wn = wid >> 1;
    const int g    = lane >> 2, t4 = lane & 3;

    const int lr = t >> 2;             // 0..63
    const int lw = (t & 3) * 2;        // word offset 0,2,4,6
    const float* Ap = A + (size_t)(m0 + lr) * HIDC + (t & 3) * 4;
    const float* Bp = B + (size_t)(n0 + lr) * HIDC + (t & 3) * 4;

    float acc[4][4][4];
#pragma unroll
    for (int i = 0; i < 4; i++)
#pragma unroll
        for (int j = 0; j < 4; j++)
#pragma unroll
            for (int r = 0; r < 4; r++) acc[i][j][r] = 0.f;

    float4 ra0, ra1, rb0, rb1;
    auto gload = [&](int kt) {
        const float* a = Ap + kt * 16;
        const float* b = Bp + kt * 16;
        ra0 = *(const float4*)(a);
        ra1 = *(const float4*)(a + (size_t)64 * HIDC);
        rb0 = *(const float4*)(b);
        rb1 = *(const float4*)(b + (size_t)64 * HIDC);
    };
    auto sts = [&](int st) {
        uint32_t h0, l0, h1, l1;
        cvt_pair(ra0.x, ra0.y, h0, l0); cvt_pair(ra0.z, ra0.w, h1, l1);
        sAh[st][lr * LDB + lw] = h0; sAh[st][lr * LDB + lw + 1] = h1;
        sAl[st][lr * LDB + lw] = l0; sAl[st][lr * LDB + lw + 1] = l1;
        cvt_pair(ra1.x, ra1.y, h0, l0); cvt_pair(ra1.z, ra1.w, h1, l1);
        sAh[st][(lr + 64) * LDB + lw] = h0; sAh[st][(lr + 64) * LDB + lw + 1] = h1;
        sAl[st][(lr + 64) * LDB + lw] = l0; sAl[st][(lr + 64) * LDB + lw + 1] = l1;
        cvt_pair(rb0.x, rb0.y, h0, l0); cvt_pair(rb0.z, rb0.w, h1, l1);
        sBh[st][lr * LDB + lw] = h0; sBh[st][lr * LDB + lw + 1] = h1;
        sBl[st][lr * LDB + lw] = l0; sBl[st][lr * LDB + lw + 1] = l1;
        cvt_pair(rb1.x, rb1.y, h0, l0); cvt_pair(rb1.z, rb1.w, h1, l1);
        sBh[st][(lr + 64) * LDB + lw] = h0; sBh[st][(lr + 64) * LDB + lw + 1] = h1;
        sBl[st][(lr + 64) * LDB + lw] = l0; sBl[st][(lr + 64) * LDB + lw + 1] = l1;
    };

    gload(0);
    sts(0);
    __syncthreads();

    for (int kt = 0; kt < HIDC / 16; kt++) {
        const int st = kt & 1;
        if (kt + 1 < HIDC / 16) gload(kt + 1);

        // compute current stage: 48 bf16 mma
        uint32_t bh[4][2], bl[4][2];
#pragma unroll
        for (int nf = 0; nf < 4; nf++) {
            const int n = (wn * 32 + nf * 8 + g) * LDB;
            bh[nf][0] = sBh[st][n + t4];
            bh[nf][1] = sBh[st][n + t4 + 4];
            bl[nf][0] = sBl[st][n + t4];
            bl[nf][1] = sBl[st][n + t4 + 4];
        }
#pragma unroll
        for (int mf = 0; mf < 4; mf++) {
            const int m = (wm * 64 + mf * 16 + g) * LDB;
            uint32_t ah[4], al[4];
            ah[0] = sAh[st][m + t4];
            ah[1] = sAh[st][m + 8 * LDB + t4];
            ah[2] = sAh[st][m + t4 + 4];
            ah[3] = sAh[st][m + 8 * LDB + t4 + 4];
            al[0] = sAl[st][m + t4];
            al[1] = sAl[st][m + 8 * LDB + t4];
            al[2] = sAl[st][m + t4 + 4];
            al[3] = sAl[st][m + 8 * LDB + t4 + 4];
#pragma unroll
            for (int nf = 0; nf < 4; nf++) {
                mma_bf16(acc[mf][nf], ah, bh[nf]);
                mma_bf16(acc[mf][nf], ah, bl[nf]);
                mma_bf16(acc[mf][nf], al, bh[nf]);
            }
        }

        if (kt + 1 < HIDC / 16) {
            sts((kt + 1) & 1);
            __syncthreads();
        }
    }

#pragma unroll
    for (int mf = 0; mf < 4; mf++) {
#pragma unroll
        for (int nf = 0; nf < 4; nf++) {
            const int row = m0 + wm * 64 + mf * 16 + g;
            const int col = n0 + wn * 32 + nf * 8 + t4 * 2;
            float2 bb = *(const float2*)(bias + col);
            float2 o0, o1;
            o0.x = acc[mf][nf][0] + bb.x;
            o0.y = acc[mf][nf][1] + bb.y;
            o1.x = acc[mf][nf][2] + bb.x;
            o1.y = acc[mf][nf][3] + bb.y;
            if (resid != nullptr) {
                float2 r0 = *(const float2*)(resid + (size_t)row * HIDC + col);
                float2 r1 = *(const float2*)(resid + (size_t)(row + 8) * HIDC + col);
                o0.x += r0.x; o0.y += r0.y;
                o1.x += r1.x; o1.y += r1.y;
            }
            *(float2*)(C + (size_t)row * HIDC + col)       = o0;
            *(float2*)(C + (size_t)(row + 8) * HIDC + col) = o1;
        }
    }
}

__global__ __launch_bounds__(256, 2) void qkv_gemm(const float* __restrict__ H,
    const float* __restrict__ Wq, const float* __restrict__ bq,
    const float* __restrict__ Wk, const float* __restrict__ bk,
    const float* __restrict__ Wv, const float* __restrict__ bv)
{
    const float* W;
    const float* bias;
    float* out;
    if (blockIdx.z == 0)      { W = Wq; bias = bq; out = g_q; }
    else if (blockIdx.z == 1) { W = Wk; bias = bk; out = g_k; }
    else                      { W = Wv; bias = bv; out = g_v; }
    gemm_tc_body(H, W, bias, nullptr, out);
}

__global__ __launch_bounds__(256, 2) void o_gemm(const float* __restrict__ Wo,
    const float* __restrict__ bo, const float* __restrict__ H)
{
    gemm_tc_body(g_ctx, Wo, bo, H, g_x);
}

// ---------------------------------------------------------------------------
// Tensor-core fused attention. Per block: (b, h, 32 q-rows).
//  Phase 1: S = (Q K^T + bias)/sqrt(32) via 3xBF16 m16n8k16
//  Phase 2: exact softmax; write probs; normalized P back to S
//  Phase 3: ctx^T = V^T P^T via 3xTF32 m16n8k8 (unchanged)
// ---------------------------------------------------------------------------
constexpr int SST  = 1032;  // S smem row stride (floats)
constexpr int KSTB = 20;    // phase-1 bf16 row stride (words; 16 used)
constexpr int KST  = 33;    // phase-3 tf32 row stride (words)

constexpr int OFF_S  = 0;                 // 32*1032 = 33024 floats
constexpr int OFF_KH = 33024;             // 256*33 = 8448 (max of both uses)
constexpr int OFF_KL = OFF_KH + 8448;     // 8448
constexpr int OFF_QH = OFF_KL + 8448;     // 1056
constexpr int OFF_QL = OFF_QH + 1056;     // 1056
constexpr int OFF_BS = OFF_QL + 1056;     // 1056
constexpr int ATTN_FLOATS = OFF_BS + 1056;  // 53088
constexpr size_t ATTN_SMEM_BYTES = (size_t)ATTN_FLOATS * sizeof(float);

__global__ __launch_bounds__(256, 1) void attn_kernel(const float* __restrict__ dist_emb,
                                                      float* __restrict__ probs_out)
{
    extern __shared__ float sm[];
    float*    S  = sm + OFF_S;
    uint32_t* kh = (uint32_t*)(sm + OFF_KH);
    uint32_t* kl = (uint32_t*)(sm + OFF_KL);
    uint32_t* qh = (uint32_t*)(sm + OFF_QH);
    uint32_t* ql = (uint32_t*)(sm + OFF_QL);
    float*    bs = sm + OFF_BS;

    const int t   = threadIdx.x;
    const int q0  = blockIdx.x * 32;
    const int h   = blockIdx.y;
    const int b   = blockIdx.z;
    const int wid = t >> 5, lane = t & 31;
    const int g   = lane >> 2, t4 = lane & 3;

    const size_t bh_off = (size_t)b * SEQ * HIDC + (size_t)h * HDC;
    const float* Qb = g_q + bh_off;
    const float* Kb = g_k + bh_off;
    const float* Vb = g_v + bh_off;

    // bias strip: bs[r] = dist_emb[(q0 + r)*HD + h], r in [0,1054]
    for (int r = t; r < 1055; r += 256)
        bs[r] = dist_emb[(size_t)(q0 + r) * HDC + h];

    // stage Q tile (32x32) as bf16 hi/lo pair-words
    {
        const int row = t >> 3, c4 = (t & 7) * 4, w2 = (t & 7) * 2;
        float4 v = *(const float4*)(Qb + (size_t)(q0 + row) * HIDC + c4);
        uint32_t h0, l0, h1, l1;
        cvt_pair(v.x, v.y, h0, l0);
        cvt_pair(v.z, v.w, h1, l1);
        qh[row * KSTB + w2]     = h0;
        qh[row * KSTB + w2 + 1] = h1;
        ql[row * KSTB + w2]     = l0;
        ql[row * KSTB + w2 + 1] = l1;
    }
    __syncthreads();

    // preload Q A-fragments (m16n8k16): [mf][ks][4]
    uint32_t qfh[2][2][4], qfl[2][2][4];
#pragma unroll
    for (int mf = 0; mf < 2; mf++)
#pragma unroll
        for (int ks = 0; ks < 2; ks++) {
            const int r0 = (mf * 16 + g) * KSTB;
            const int r1 = r0 + 8 * KSTB;
            const int k0 = ks * 8 + t4;
            qfh[mf][ks][0] = qh[r0 + k0];
            qfh[mf][ks][1] = qh[r1 + k0];
            qfh[mf][ks][2] = qh[r0 + k0 + 4];
            qfh[mf][ks][3] = qh[r1 + k0 + 4];
            qfl[mf][ks][0] = ql[r0 + k0];
            qfl[mf][ks][1] = ql[r1 + k0];
            qfl[mf][ks][2] = ql[r0 + k0 + 4];
            qfl[mf][ks][3] = ql[r1 + k0 + 4];
        }

    const float scale = 0.17677669529663688f;  // 1/sqrt(32)

    // ---- Phase 1: S = (Q K^T + bias) * scale ----
    for (int c = 0; c < 4; c++) {
        __syncthreads();
        // stage K chunk (256x32) as bf16 hi/lo
#pragma unroll
        for (int p = 0; p < 8; p++) {
            const int row = p * 32 + (t >> 3), c4 = (t & 7) * 4, w2 = (t & 7) * 2;
            float4 v = *(const float4*)(Kb + (size_t)(c * 256 + row) * HIDC + c4);
            uint32_t h0, l0, h1, l1;
            cvt_pair(v.x, v.y, h0, l0);
            cvt_pair(v.z, v.w, h1, l1);
            kh[row * KSTB + w2]     = h0;
            kh[row * KSTB + w2 + 1] = h1;
            kl[row * KSTB + w2]     = l0;
            kl[row * KSTB + w2 + 1] = l1;
        }
        __syncthreads();

        const int kw = wid * 32;   // this warp's 32 keys within chunk
#pragma unroll
        for (int nf = 0; nf < 4; nf++) {
            uint32_t bhh[2][2], bll[2][2];
#pragma unroll
            for (int ks = 0; ks < 2; ks++) {
                const int n = (kw + nf * 8 + g) * KSTB + ks * 8 + t4;
                bhh[ks][0] = kh[n]; bhh[ks][1] = kh[n + 4];
                bll[ks][0] = kl[n]; bll[ks][1] = kl[n + 4];
            }
#pragma unroll
            for (int mf = 0; mf < 2; mf++) {
                float acc[4] = {0.f, 0.f, 0.f, 0.f};
#pragma unroll
                for (int ks = 0; ks < 2; ks++) {
                    mma_bf16(acc, qfh[mf][ks], bhh[ks]);
                    mma_bf16(acc, qfh[mf][ks], bll[ks]);
                    mma_bf16(acc, qfl[mf][ks], bhh[ks]);
                }
                const int row0 = mf * 16 + g;
                const int row1 = row0 + 8;
                const int col  = c * 256 + kw + nf * 8 + 2 * t4;
                float2 s0, s1;
                s0.x = (acc[0] + bs[row0 - col + 1023]) * scale;
                s0.y = (acc[1] + bs[row0 - col + 1022]) * scale;
                s1.x = (acc[2] + bs[row1 - col + 1023]) * scale;
                s1.y = (acc[3] + bs[row1 - col + 1022]) * scale;
                *(float2*)&S[row0 * SST + col] = s0;
                *(float2*)&S[row1 * SST + col] = s1;
            }
        }
    }
    __syncthreads();

    // ---- Phase 2: softmax; write probs; normalized P back to S ----
    {
        float* pb = probs_out + ((size_t)(b * NHC + h) * SEQ + q0) * SEQ;
        for (int rr = 0; rr < 4; rr++) {
            const int r = wid + 8 * rr;
            float* row = S + r * SST;
            float mx = -1e30f;
            for (int i = lane; i < 1024; i += 32) mx = fmaxf(mx, row[i]);
#pragma unroll
            for (int o = 16; o > 0; o >>= 1)
                mx = fmaxf(mx, __shfl_xor_sync(0xffffffffu, mx, o));
            float sum = 0.f;
            for (int i = lane; i < 1024; i += 32) {
                float e = __expf(row[i] - mx);
                row[i] = e;
                sum += e;
            }
#pragma unroll
            for (int o = 16; o > 0; o >>= 1)
                sum += __shfl_xor_sync(0xffffffffu, sum, o);
            const float inv = 1.f / sum;
            float* pr = pb + (size_t)r * SEQ;
            for (int i = lane; i < 1024; i += 32) {
                float p = row[i] * inv;
                row[i] = p;
                pr[i]  = p;
            }
        }
    }

    // ---- Phase 3: ctx^T = V^T @ P^T via 3xTF32 (m=dim, n=q-row, k=key) ----
    float acc[2][4][4];
#pragma unroll
    for (int mf = 0; mf < 2; mf++)
#pragma unroll
        for (int nf = 0; nf < 4; nf++)
#pragma unroll
            for (int r = 0; r < 4; r++) acc[mf][nf][r] = 0.f;

    for (int c = 0; c < 4; c++) {
        __syncthreads();
        // stage V chunk (256x32) as tf32 hi/lo (stride KST=33)
#pragma unroll
        for (int p = 0; p < 8; p++) {
            const int row = p * 32 + (t >> 3), c4 = (t & 7) * 4;
            float4 v = *(const float4*)(Vb + (size_t)(c * 256 + row) * HIDC + c4);
            float vv[4] = {v.x, v.y, v.z, v.w};
#pragma unroll
            for (int j = 0; j < 4; j++) {
                uint32_t hi = f2tf32(vv[j]);
                kh[row * KST + c4 + j] = hi;
                kl[row * KST + c4 + j] = f2tf32(vv[j] - __uint_as_float(hi));
            }
        }
        __syncthreads();

        const int kw = wid * 32;
#pragma unroll
        for (int ks = 0; ks < 4; ks++) {
            const int kLoc  = kw + ks * 8 + t4;
            const int kGlob = c * 256 + kLoc;
            uint32_t ah[2][4], al[2][4];
#pragma unroll
            for (int mf = 0; mf < 2; mf++) {
                const int d0 = mf * 16 + g;
                const int a0 = kLoc * KST + d0;
                const int a4 = (kLoc + 4) * KST + d0;
                ah[mf][0] = kh[a0];
                ah[mf][1] = kh[a0 + 8];
                ah[mf][2] = kh[a4];
                ah[mf][3] = kh[a4 + 8];
                al[mf][0] = kl[a0];
                al[mf][1] = kl[a0 + 8];
                al[mf][2] = kl[a4];
                al[mf][3] = kl[a4 + 8];
            }
#pragma unroll
            for (int nf = 0; nf < 4; nf++) {
                const int q = nf * 8 + g;
                const float p0 = S[q * SST + kGlob];
                const float p1 = S[q * SST + kGlob + 4];
                uint32_t bh2[2], bl2[2];
                bh2[0] = f2tf32(p0); bl2[0] = f2tf32(p0 - __uint_as_float(bh2[0]));
                bh2[1] = f2tf32(p1); bl2[1] = f2tf32(p1 - __uint_as_float(bh2[1]));
#pragma unroll
                for (int mf = 0; mf < 2; mf++) {
                    mma_tf32(acc[mf][nf], ah[mf], bh2);
                    mma_tf32(acc[mf][nf], ah[mf], bl2);
                    mma_tf32(acc[mf][nf], al[mf], bh2);
                }
            }
        }
    }
    __syncthreads();

    // cross-warp reduction of partial ctx
    float* red = sm + OFF_KH;
#pragma unroll
    for (int mf = 0; mf < 2; mf++)
#pragma unroll
        for (int nf = 0; nf < 4; nf++) {
            const int d = mf * 16 + g;
            const int q = nf * 8 + 2 * t4;
            float* rw = red + wid * 1056;
            rw[q * 33 + d]           = acc[mf][nf][0];
            rw[(q + 1) * 33 + d]     = acc[mf][nf][1];
            rw[q * 33 + d + 8]       = acc[mf][nf][2];
            rw[(q + 1) * 33 + d + 8] = acc[mf][nf][3];
        }
    __syncthreads();

#pragma unroll
    for (int i = 0; i < 4; i++) {
        const int idx = t + i * 256;
        const int q = idx >> 5, d = idx & 31;
        float s = 0.f;
#pragma unroll
        for (int w = 0; w < 8; w++) s += red[w * 1056 + q * 33 + d];
        g_ctx[(size_t)(b * SEQ + q0 + q) * HIDC + h * HDC + d] = s;
    }
}

// ---------------------------------------------------------------------------
// LayerNorm (unchanged)
// ---------------------------------------------------------------------------
__global__ void ln_kernel(const float* __restrict__ gamma,
                          const float* __restrict__ beta,
                          float* __restrict__ out)
{
    __shared__ float red[8];
    const int row = blockIdx.x, t = threadIdx.x;
    const int w = t >> 5, lane = t & 31;

    float4 v = *((const float4*)(g_x + (size_t)row * HIDC) + t);
    float s = v.x + v.y + v.z + v.w;
#pragma unroll
    for (int o = 16; o > 0; o >>= 1) s += __shfl_xor_sync(0xffffffffu, s, o);
    if (lane == 0) red[w] = s;
    __syncthreads();
    if (t == 0) {
        float tt = 0.f;
#pragma unroll
        for (int i = 0; i < 8; i++) tt += red[i];
        red[0] = tt;
    }
    __syncthreads();
    const float mu = red[0] * (1.f / 1024.f);
    __syncthreads();

    float dx = v.x - mu, dy = v.y - mu, dz = v.z - mu, dw = v.w - mu;
    float sq = dx * dx + dy * dy + dz * dz + dw * dw;
#pragma unroll
    for (int o = 16; o > 0; o >>= 1) sq += __shfl_xor_sync(0xffffffffu, sq, o);
    if (lane == 0) red[w] = sq;
    __syncthreads();
    if (t == 0) {
        float tt = 0.f;
#pragma unroll
        for (int i = 0; i < 8; i++) tt += red[i];
        red[0] = tt;
    }
    __syncthreads();
    const float inv = rsqrtf(red[0] * (1.f / 1024.f) + 1e-12f);

    float4 g  = *((const float4*)gamma + t);
    float4 bt = *((const float4*)beta + t);
    float4 o4;
    o4.x = dx * inv * g.x + bt.x;
    o4.y = dy * inv * g.y + bt.y;
    o4.z = dz * inv * g.z + bt.z;
    o4.w = dw * inv * g.w + bt.w;
    *((float4*)(out + (size_t)row * HIDC) + t) = o4;
}

// ---------------------------------------------------------------------------
// Launch
// ---------------------------------------------------------------------------
extern "C" void kernel_launch(void* const* d_in, const int* in_sizes, int n_in,
                              void* d_out, int out_size)
{
    (void)in_sizes; (void)n_in; (void)out_size;
    const float* hidden = (const float*)d_in[0];
    const float* Wq = (const float*)d_in[1];
    const float* bq = (const float*)d_in[2];
    const float* Wk = (const float*)d_in[3];
    const float* bk = (const float*)d_in[4];
    const float* Wv = (const float*)d_in[5];
    const float* bv = (const float*)d_in[6];
    const float* Wo = (const float*)d_in[7];
    const float* bo = (const float*)d_in[8];
    const float* gamma = (const float*)d_in[9];
    const float* beta  = (const float*)d_in[10];
    const float* dist  = (const float*)d_in[11];

    float* out   = (float*)d_out;
    float* probs = out + (size_t)BATCH * SEQ * HIDC;

    cudaFuncSetAttribute(attn_kernel, cudaFuncAttributeMaxDynamicSharedMemorySize,
                         (int)ATTN_SMEM_BYTES);

    qkv_gemm<<<dim3(8, 32, 3), 256>>>(hidden, Wq, bq, Wk, bk, Wv, bv);
    attn_kernel<<<dim3(32, 32, 4), 256, ATTN_SMEM_BYTES>>>(dist, probs);
    o_gemm<<<dim3(8, 32, 1), 256>>>(Wo, bo, hidden);
    ln_kernel<<<MR, 256>>>(gamma, beta, out);
}